// round 10
// baseline (speedup 1.0000x reference)
#include <cuda_runtime.h>
#include <cstdint>

#define B_   64
#define T_   512
#define H_   512
#define E_   128
#define C_   1000
#define G7   (7 * H_)    // 3584
#define OUTW (6 * H_)    // 3072
#define NCTA 128
#define NTHR 512

typedef unsigned long long ull;

// ---- device-global scratch ----
__device__ float g_tg[C_ * G7];        // table_gates = emb @ W1 + b   (14.3 MB)
__device__ float g_h[2][H_ * B_];      // h_d double buffer, [buf][k*64+b]
__device__ int           g_count;      // init-barrier counter (atomic, used 2x)
__device__ volatile int  g_sense;      // init-barrier sense (2 flips -> returns 0)
__device__ volatile int  g_flags[NCTA];// per-CTA cumulative arrival counters
__device__ volatile int  g_go;         // release counter (cumulative)

// ---- helpers ----
__device__ __forceinline__ float sigf(float x)      { return 1.0f / (1.0f + expf(-x)); }
__device__ __forceinline__ float softplusf(float x) { return fmaxf(x, 0.0f) + log1pf(expf(-fabsf(x))); }

__device__ __forceinline__ void ffma2(ull& d, ull a, ull b)
{
    asm("fma.rn.f32x2 %0, %1, %2, %0;" : "+l"(d) : "l"(a), "l"(b));
}
__device__ __forceinline__ ull dup2(float w)
{
    ull d; unsigned u = __float_as_uint(w);
    asm("mov.b64 %0, {%1, %1};" : "=l"(d) : "r"(u));
    return d;
}
__device__ __forceinline__ uint32_t smem_u32(const void* p)
{
    uint32_t a;
    asm("{ .reg .u64 t; cvta.to.shared.u64 t, %1; cvt.u32.u64 %0, t; }" : "=r"(a) : "l"(p));
    return a;
}
__device__ __forceinline__ void mbar_init(uint32_t mbar, uint32_t cnt)
{
    asm volatile("mbarrier.init.shared.b64 [%0], %1;" :: "r"(mbar), "r"(cnt) : "memory");
}
__device__ __forceinline__ void mbar_expect_tx(uint32_t mbar, uint32_t bytes)
{
    asm volatile("mbarrier.arrive.expect_tx.shared.b64 _, [%0], %1;" :: "r"(mbar), "r"(bytes) : "memory");
}
__device__ __forceinline__ void bulk_ldgsts(uint32_t dst, const void* src, uint32_t bytes, uint32_t mbar)
{
    asm volatile("cp.async.bulk.shared::cta.global.mbarrier::complete_tx::bytes [%0], [%1], %2, [%3];"
                 :: "r"(dst), "l"(src), "r"(bytes), "r"(mbar) : "memory");
}
__device__ __forceinline__ void mbar_wait(uint32_t mbar, uint32_t parity)
{
    uint32_t done;
    asm volatile(
        "{\n\t.reg .pred p;\n\t"
        "mbarrier.try_wait.parity.acquire.cta.shared::cta.b64 p, [%1], %2;\n\t"
        "selp.b32 %0, 1, 0, p;\n\t}"
        : "=r"(done) : "r"(mbar), "r"(parity) : "memory");
    if (!done) {
        asm volatile(
            "{\n\t.reg .pred P1;\n\t"
            "WL_%=:\n\t"
            "mbarrier.try_wait.parity.acquire.cta.shared::cta.b64 P1, [%0], %1, 0x989680;\n\t"
            "@P1 bra.uni WD_%=;\n\t"
            "bra.uni WL_%=;\n\t"
            "WD_%=:\n\t}"
            :: "r"(mbar), "r"(parity) : "memory");
    }
}
__device__ __forceinline__ void fence_proxy_async_()
{
    asm volatile("fence.proxy.async;" ::: "memory");
}

// atomic grid sync — used only twice at init (even sense flips; replay safe)
__device__ __forceinline__ void grid_sync_init(int* sense)
{
    __threadfence();
    __syncthreads();
    if (threadIdx.x == 0) {
        int s = *sense ^ 1;
        *sense = s;
        if (atomicAdd(&g_count, 1) == (int)gridDim.x - 1) {
            g_count = 0;
            __threadfence();
            g_sense = s;
        } else {
            while (g_sense != s) { __nanosleep(64); }
            __threadfence();
        }
    }
    __syncthreads();
}

// =====================  Kernel 1: table_gates  =====================
__global__ void tg_kernel(const float* __restrict__ emb,
                          const float* __restrict__ W,
                          const float* __restrict__ bias)
{
    __shared__ float sh_e[16][E_];
    const int col = blockIdx.x * 256 + threadIdx.x;
    const int c0  = blockIdx.y * 16;

    for (int i = threadIdx.x; i < 16 * E_; i += 256) {
        int ci = i >> 7, e = i & 127;
        int c  = c0 + ci;
        sh_e[ci][e] = (c < C_) ? emb[c * E_ + e] : 0.0f;
    }
    __syncthreads();

    float acc[16];
#pragma unroll
    for (int i = 0; i < 16; ++i) acc[i] = 0.0f;

    for (int e = 0; e < E_; ++e) {
        float wv = W[e * G7 + col];
#pragma unroll
        for (int i = 0; i < 16; ++i) acc[i] = fmaf(sh_e[i][e], wv, acc[i]);
    }
    float bb = bias[col];
#pragma unroll
    for (int i = 0; i < 16; ++i) {
        int c = c0 + i;
        if (c < C_) g_tg[c * G7 + col] = acc[i] + bb;
    }
}

// =====================  Kernel 2: persistent recurrence  =====================
// Identical compute structure to R9; only the per-step grid barrier changed:
// contention-free per-CTA flags + parallel aggregation in CTA0 + single release word.
#define WS_F    (512 * 32)            // 16384 floats = 65536 B  (W scalar, [k][jl][g8])
#define HB_F    (128 * 64)            //  8192 floats = 32768 B per buffer
#define HBUF_BYTES 32768
#define RSTRIDE 30                    // floats per reduction record
#define RED_F   (256 * RSTRIDE)       // 7680 floats = 30720 B (tree reduction)
#define MBAR_OFF ((WS_F + 4 * HB_F + RED_F) * 4)     // 227328
#define SMEM_BYTES (MBAR_OFF + 64)                   // 227392

__global__ void __launch_bounds__(NTHR, 1)
rec_kernel(const int*   __restrict__ marks,
           const float* __restrict__ ts,
           const float* __restrict__ Wc,
           const float* __restrict__ init,
           float*       __restrict__ out)
{
    extern __shared__ float smem[];
    float* sh_W   = smem;                         // 64KB
    float* sh_hb  = smem + WS_F;                  // 4 x 32KB
    float* sh_red = sh_hb + 4 * HB_F;             // 30KB
    const uint32_t mb  = smem_u32((char*)smem + MBAR_OFF);  // full[c] = mb + 8c
    const uint32_t hb0 = smem_u32(sh_hb);

    const int tid = threadIdx.x;
    const int cta = blockIdx.x;
    const int ks  = tid >> 6;        // 0..7
    const int r   = tid & 63;
    const int jl  = r & 3;
    const int q4  = (r >> 2) * 4;

    const int eb  = tid >> 2;        // 0..63 (epilogue, tid<256)
    const int ejl = tid & 3;
    const int ej  = cta * 4 + ejl;

    // ---- init: mbarriers + own barrier flag ----
    if (tid == 0) {
#pragma unroll
        for (int c = 0; c < 4; ++c) mbar_init(mb + 8 * c, 1);
        g_flags[cta] = 0;
        if (cta == 0) g_go = 0;
    }

    // ---- load resident W slice: [k][jl][g pad8] scalar ----
    for (int idx = tid; idx < WS_F; idx += NTHR) {
        int k = idx >> 5; int rem = idx & 31;
        int jj = rem >> 3, g = rem & 7;
        sh_W[idx] = (g < 7) ? Wc[(size_t)(E_ + k) * G7 + g * H_ + cta * 4 + jj] : 0.0f;
    }

    // ---- init h buffer ----
    for (int idx = tid; idx < 4 * 64; idx += NTHR) {
        int jj = idx >> 6, bb = idx & 63;
        g_h[0][(cta * 4 + jj) * B_ + bb] = tanhf(init[cta * 4 + jj]);
    }

    // ---- output row t=0 ----
    for (int idx = tid; idx < 4 * 6 * 64; idx += NTHR) {
        int bb = idx & 63; int rest = idx >> 6;
        int f = rest % 6; int jj = rest / 6;
        int jg = cta * 4 + jj;
        float v;
        switch (f) {
            case 0:  v = tanhf(init[0 * H_ + jg]);     break;
            case 1:  v = sigf (init[5 * H_ + jg]);     break;
            case 2:  v = tanhf(init[2 * H_ + jg]);     break;
            case 3:  v = tanhf(init[3 * H_ + jg]);     break;
            case 4:  v = softplusf(init[4 * H_ + jg]); break;
            default: v = tanhf(init[1 * H_ + jg]);     break;
        }
        out[(size_t)bb * (513 * OUTW) + f * H_ + jg] = v;
    }

    // ---- per-(b,j) recurrent state (epilogue threads) ----
    float c_d = tanhf(init[H_ + ej]);
    float c_b = tanhf(init[2 * H_ + ej]);

    // ---- two init grid syncs: flags/h0 visible everywhere; sense parity even ----
    int sense = 0;
    grid_sync_init(&sense);
    grid_sync_init(&sense);

    int fph = 0;   // shared phase for all 4 full barriers (each flips once/step)

#define STEP(hp, wp) do {                                                       \
        ull hx = *(const ull*)(hp);                                             \
        ull hy = *(const ull*)((hp) + 2);                                       \
        float4 wA = *(const float4*)(wp);                                       \
        float2 wB = *(const float2*)((wp) + 4);                                 \
        float  wC = (wp)[6];                                                    \
        ull w;                                                                  \
        w = dup2(wA.x); ffma2(acc[0],  w, hx); ffma2(acc[1],  w, hy);           \
        w = dup2(wA.y); ffma2(acc[2],  w, hx); ffma2(acc[3],  w, hy);           \
        w = dup2(wA.z); ffma2(acc[4],  w, hx); ffma2(acc[5],  w, hy);           \
        w = dup2(wA.w); ffma2(acc[6],  w, hx); ffma2(acc[7],  w, hy);           \
        w = dup2(wB.x); ffma2(acc[8],  w, hx); ffma2(acc[9],  w, hy);           \
        w = dup2(wB.y); ffma2(acc[10], w, hx); ffma2(acc[11], w, hy);           \
        w = dup2(wC);   ffma2(acc[12], w, hx); ffma2(acc[13], w, hy);           \
    } while (0)

#define COMPUTE_CHUNK(c) do {                                                   \
        const float* hp = sh_hb + (c) * HB_F + (ks * 16) * 64 + q4;             \
        const float* wp = sh_W + (size_t)((128 * (c) + ks * 16) * 4 + jl) * 8;  \
        _Pragma("unroll 8")                                                     \
        for (int m = 0; m < 16; ++m) { STEP(hp, wp); hp += 64; wp += 32; }      \
    } while (0)

    for (int t = 0; t < T_; ++t) {
        const char* hsrc = (const char*)&g_h[t & 1][0];

        // ---- thread 0: stage all four h chunks ----
        if (tid == 0) {
            fence_proxy_async_();
#pragma unroll
            for (int c = 0; c < 4; ++c) {
                mbar_expect_tx(mb + 8 * c, HBUF_BYTES);
                bulk_ldgsts(hb0 + c * HBUF_BYTES, hsrc + c * HBUF_BYTES, HBUF_BYTES, mb + 8 * c);
            }
        }

        // ---- epilogue prefetch ----
        float tsv = 0.f, tsp = 0.f, tg[7];
        if (tid < 256) {
            int m = __ldg(&marks[eb * T_ + t]);
            tsv   = __ldg(&ts[eb * T_ + t]);
            tsp   = (t > 0) ? __ldg(&ts[eb * T_ + t - 1]) : 0.0f;
            const float* tgp = g_tg + (size_t)m * G7 + ej;
#pragma unroll
            for (int g = 0; g < 7; ++g) tg[g] = __ldcg(tgp + g * H_);
        }

        ull acc[14];
#pragma unroll
        for (int i = 0; i < 14; ++i) acc[i] = 0ull;

        mbar_wait(mb + 0,  fph); COMPUTE_CHUNK(0);
        mbar_wait(mb + 8,  fph); COMPUTE_CHUNK(1);
        mbar_wait(mb + 16, fph); COMPUTE_CHUNK(2);
        mbar_wait(mb + 24, fph); COMPUTE_CHUNK(3);
        fph ^= 1;

        // ---- tree reduction: round 1 ----
        if (tid >= 256) {
            ull* rb = (ull*)(sh_red + (size_t)(tid - 256) * RSTRIDE);
#pragma unroll
            for (int i = 0; i < 14; ++i) rb[i] = acc[i];
        }
        __syncthreads();

        // ---- round 2 ----
        if (tid < 256) {
            float2* af = (float2*)acc;
            const float2* rp = (const float2*)(sh_red + (size_t)tid * RSTRIDE);
#pragma unroll
            for (int i = 0; i < 14; ++i) {
                float2 v = rp[i];
                af[i].x += v.x; af[i].y += v.y;
            }
            ull* rb = (ull*)(sh_red + (size_t)tid * RSTRIDE);
#pragma unroll
            for (int i = 0; i < 14; ++i) rb[i] = acc[i];
        }
        __syncthreads();

        // ---- epilogue: 256 threads, one (b,j) each ----
        float go = 0.f, cb = 0.f, c = 0.f, gd = 0.f, cd = 0.f, hd = 0.f;
        if (tid < 256) {
            const int r_src = ((eb >> 2) << 2) | ejl;
            const int fidx  = eb & 3;
            float a[7];
#pragma unroll
            for (int g = 0; g < 7; ++g) a[g] = 0.0f;
#pragma unroll
            for (int s = 0; s < 4; ++s) {
                const float* rp = sh_red + (size_t)(s * 64 + r_src) * RSTRIDE;
#pragma unroll
                for (int g = 0; g < 7; ++g) a[g] += rp[g * 4 + fidx];
            }

            float dur = tsv - tsp;
            float gi  = sigf (a[0] + tg[0]);
            float gf  = sigf (a[1] + tg[1]);
            float gz  = tanhf(a[2] + tg[2]);
            go  = sigf (a[3] + tg[3]);
            float gib = sigf (a[4] + tg[4]);
            float gfb = sigf (a[5] + tg[5]);
            gd  = softplusf(a[6] + tg[6]);

            c  = gf * c_d + gi * gz;
            cb = gfb * c_b + gib * gz;
            cd = cb + (c - cb) * expf(-gd * dur);
            hd = go * tanhf(cd);
            c_d = cd; c_b = cb;

            g_h[(t + 1) & 1][ej * B_ + eb] = hd;   // publish h first
        }

        // ---- flag barrier: arrive ----
        const bool last = (t == T_ - 1);
        __threadfence();
        __syncthreads();
        if (tid == 0 && !last) g_flags[cta] = t + 1;     // own slot, no contention

        // ---- hidden under the wait: output STGs ----
        if (tid < 256) {
            size_t ob = (size_t)eb * (513 * OUTW) + (size_t)(t + 1) * OUTW + ej;
            out[ob]          = hd;
            out[ob + 1 * H_] = go;
            out[ob + 2 * H_] = cb;
            out[ob + 3 * H_] = c;
            out[ob + 4 * H_] = gd;
            out[ob + 5 * H_] = cd;
        }

        // ---- flag barrier: aggregate (CTA0, parallel) + release + wait ----
        if (!last) {
            if (cta == 0) {
                if (tid < NCTA) {
                    while (g_flags[tid] < t + 1) { }
                }
                __syncthreads();
                if (tid == 0) { __threadfence(); g_go = t + 1; }
            }
            if (tid == 0) {
                while (g_go < t + 1) { }
                __threadfence();
            }
            __syncthreads();
        }
    }
#undef COMPUTE_CHUNK
#undef STEP
}

// =====================  launch  =====================
extern "C" void kernel_launch(void* const* d_in, const int* in_sizes, int n_in,
                              void* d_out, int out_size)
{
    const int*   marks = (const int*)  d_in[0];
    const float* ts    = (const float*)d_in[1];
    const float* emb   = (const float*)d_in[2];
    const float* Wc    = (const float*)d_in[3];
    const float* bc    = (const float*)d_in[4];
    const float* init  = (const float*)d_in[5];
    float*       out   = (float*)d_out;

    dim3 g1(G7 / 256, (C_ + 15) / 16);
    tg_kernel<<<g1, 256>>>(emb, Wc, bc);

    cudaFuncSetAttribute(rec_kernel, cudaFuncAttributeMaxDynamicSharedMemorySize, SMEM_BYTES);
    rec_kernel<<<NCTA, NTHR, SMEM_BYTES>>>(marks, ts, Wc, init, out);
}

// round 12
// speedup vs baseline: 1.3813x; 1.3813x over previous
#include <cuda_runtime.h>
#include <cuda_bf16.h>
#include <cstdint>

#define B_   64
#define T_   512
#define H_   512
#define E_   128
#define C_   1000
#define G7   (7 * H_)    // 3584
#define OUTW (6 * H_)    // 3072
#define NCTA 128
#define NTHR 256

typedef unsigned long long ull;

// ---- device-global scratch ----
__device__ float g_tg[C_ * G7];                      // table_gates (14.3 MB)
__device__ __align__(128) unsigned char g_himg[2][131072];  // A-image (fragment-order bf16 hi/lo)
__device__ int           g_count;
__device__ volatile int  g_sense;

// ---- math helpers ----
__device__ __forceinline__ float sigf(float x)      { return 1.0f / (1.0f + expf(-x)); }
__device__ __forceinline__ float softplusf(float x) { return fmaxf(x, 0.0f) + log1pf(expf(-fabsf(x))); }

__device__ __forceinline__ uint32_t smem_u32(const void* p)
{
    uint32_t a;
    asm("{ .reg .u64 t; cvta.to.shared.u64 t, %1; cvt.u32.u64 %0, t; }" : "=r"(a) : "l"(p));
    return a;
}
__device__ __forceinline__ void mbar_init(uint32_t mbar, uint32_t cnt)
{
    asm volatile("mbarrier.init.shared.b64 [%0], %1;" :: "r"(mbar), "r"(cnt) : "memory");
}
__device__ __forceinline__ void mbar_expect_tx(uint32_t mbar, uint32_t bytes)
{
    asm volatile("mbarrier.arrive.expect_tx.shared.b64 _, [%0], %1;" :: "r"(mbar), "r"(bytes) : "memory");
}
__device__ __forceinline__ void bulk_ldgsts(uint32_t dst, const void* src, uint32_t bytes, uint32_t mbar)
{
    asm volatile("cp.async.bulk.shared::cta.global.mbarrier::complete_tx::bytes [%0], [%1], %2, [%3];"
                 :: "r"(dst), "l"(src), "r"(bytes), "r"(mbar) : "memory");
}
__device__ __forceinline__ void mbar_wait(uint32_t mbar, uint32_t parity)
{
    uint32_t done;
    asm volatile(
        "{\n\t.reg .pred p;\n\t"
        "mbarrier.try_wait.parity.acquire.cta.shared::cta.b64 p, [%1], %2;\n\t"
        "selp.b32 %0, 1, 0, p;\n\t}"
        : "=r"(done) : "r"(mbar), "r"(parity) : "memory");
    if (!done) {
        asm volatile(
            "{\n\t.reg .pred P1;\n\t"
            "WL_%=:\n\t"
            "mbarrier.try_wait.parity.acquire.cta.shared::cta.b64 P1, [%0], %1, 0x989680;\n\t"
            "@P1 bra.uni WD_%=;\n\t"
            "bra.uni WL_%=;\n\t"
            "WD_%=:\n\t}"
            :: "r"(mbar), "r"(parity) : "memory");
    }
}
__device__ __forceinline__ void fence_proxy_async_()
{
    asm volatile("fence.proxy.async;" ::: "memory");
}

// bf16 mma.sync (baseline PTX, sm_80+; HMMA on sm_103)
__device__ __forceinline__ void mma16816(float* d,
                                         uint32_t a0, uint32_t a1, uint32_t a2, uint32_t a3,
                                         uint32_t b0, uint32_t b1)
{
    asm volatile(
        "mma.sync.aligned.m16n8k16.row.col.f32.bf16.bf16.f32 "
        "{%0,%1,%2,%3}, {%4,%5,%6,%7}, {%8,%9}, {%0,%1,%2,%3};"
        : "+f"(d[0]), "+f"(d[1]), "+f"(d[2]), "+f"(d[3])
        : "r"(a0), "r"(a1), "r"(a2), "r"(a3), "r"(b0), "r"(b1));
}

// ---- smem layout (bytes) ----
#define A_OFF      0                  // A image: [mtile8][ktile32][lane32][reg4] x 4B = 131072
#define WF_OFF     131072             // W fragments: [pass2][ktile32][ntile4][lane32] x 8B = 65536
#define EXCH_OFF   196608             // 2 x 128 x 29 fp32 = 29696
#define MBAR_OFF   226304             // 8 chunk mbarriers
#define SMEM_BYTES (MBAR_OFF + 128)   // 226432

// A-image offset for element (m in 0..127, k in 0..511)
__device__ __forceinline__ uint32_t aimg_off(int m, int k)
{
    int mt = m >> 4, mr = m & 15;
    int kt = k >> 4, kr = k & 15;
    int lane = ((mr & 7) << 2) | ((kr >> 1) & 3);
    int reg  = ((mr >> 3) & 1) | ((kr & 8) ? 2 : 0);
    return ((((uint32_t)(mt * 32 + kt) * 32 + lane) * 4 + reg) * 4) + ((kr & 1) * 2);
}

// =====================  Kernel 1: table_gates  =====================
__global__ void tg_kernel(const float* __restrict__ emb,
                          const float* __restrict__ W,
                          const float* __restrict__ bias)
{
    __shared__ float sh_e[16][E_];
    const int col = blockIdx.x * 256 + threadIdx.x;
    const int c0  = blockIdx.y * 16;

    for (int i = threadIdx.x; i < 16 * E_; i += 256) {
        int ci = i >> 7, e = i & 127;
        int c  = c0 + ci;
        sh_e[ci][e] = (c < C_) ? emb[c * E_ + e] : 0.0f;
    }
    __syncthreads();

    float acc[16];
#pragma unroll
    for (int i = 0; i < 16; ++i) acc[i] = 0.0f;

    for (int e = 0; e < E_; ++e) {
        float wv = W[e * G7 + col];
#pragma unroll
        for (int i = 0; i < 16; ++i) acc[i] = fmaf(sh_e[i][e], wv, acc[i]);
    }
    float bb = bias[col];
#pragma unroll
    for (int i = 0; i < 16; ++i) {
        int c = c0 + i;
        if (c < C_) g_tg[c * G7 + col] = acc[i] + bb;
    }
}

// =====================  Kernel 2: persistent HMMA recurrence  =====================
// 128 CTAs x 256 threads. CTA owns gate cols n = g*4+jl for j in [4cta,4cta+4).
// Per step: D[128,32] = A(h hi/lo stacked)[128,512]bf16 x W(hi then lo)[512,32]bf16.
// a(b,n) = sum_kh( D[b,n] + D[b+64,n] ) = full-precision h . W.
__global__ void __launch_bounds__(NTHR, 1)
rec_kernel(const int*   __restrict__ marks,
           const float* __restrict__ ts,
           const float* __restrict__ Wc,
           const float* __restrict__ init,
           float*       __restrict__ out)
{
    extern __shared__ unsigned char smem[];
    uint32_t*      wf   = (uint32_t*)(smem + WF_OFF);    // [pass][kt][nt][lane] uint2
    float*         exch = (float*)(smem + EXCH_OFF);     // [kh][128][29]
    const uint32_t mb   = smem_u32(smem + MBAR_OFF);
    const uint32_t smA  = smem_u32(smem + A_OFF);

    const int tid  = threadIdx.x;
    const int cta  = blockIdx.x;
    const int lane = tid & 31;
    const int wid  = tid >> 5;
    const int kh   = wid & 1;        // k-half: ktiles [16kh,16kh+16)
    const int mp   = wid >> 1;       // m-pair: mtiles {2mp, 2mp+1}
    const int grp  = lane >> 2;
    const int tg4  = lane & 3;

    const int eb   = tid >> 2;       // 0..63  epilogue batch
    const int ejl  = tid & 3;
    const int ej   = cta * 4 + ejl;

    if (tid == 0) {
#pragma unroll
        for (int c = 0; c < 8; ++c) mbar_init(mb + 8 * c, 1);
    }

    // ---- prepack W fragments (hi pass 0 / lo pass 1), B-fragment order ----
    for (int idx = tid; idx < 8192; idx += NTHR) {
        int l    = idx & 31;
        int nt   = (idx >> 5) & 3;
        int kt   = (idx >> 7) & 31;
        int pass = idx >> 12;
        int n    = nt * 8 + (l >> 2);
        int k0   = kt * 16 + (l & 3) * 2;
        float w[4];
#pragma unroll
        for (int i = 0; i < 4; ++i) {
            int k = k0 + (i & 1) + ((i >> 1) * 8);
            float v = 0.0f;
            if (n < 28) v = Wc[(size_t)(E_ + k) * G7 + (n >> 2) * H_ + cta * 4 + (n & 3)];
            if (pass == 0) {
                w[i] = __bfloat162float(__float2bfloat16(v));
            } else {
                w[i] = v - __bfloat162float(__float2bfloat16(v));
            }
        }
        __nv_bfloat162 r0, r1;
        r0.x = __float2bfloat16(w[0]); r0.y = __float2bfloat16(w[1]);
        r1.x = __float2bfloat16(w[2]); r1.y = __float2bfloat16(w[3]);
        wf[idx * 2]     = *(uint32_t*)&r0;
        wf[idx * 2 + 1] = *(uint32_t*)&r1;
    }

    // ---- init h image t=0 (this CTA's 4 k columns, all 128 m-rows) ----
    for (int idx = tid; idx < 512; idx += NTHR) {
        int m = idx >> 2;
        int k = cta * 4 + (idx & 3);
        float v = tanhf(init[k]);
        __nv_bfloat16 hi = __float2bfloat16(v);
        __nv_bfloat16 val = (m < 64) ? hi : __float2bfloat16(v - __bfloat162float(hi));
        int mm = (m < 64) ? m : m;   // mapping uses m directly (rows 64-127 are lo block)
        *(__nv_bfloat16*)(g_himg[0] + aimg_off(mm, k)) = val;
    }

    // ---- output row t=0 ----
    for (int idx = tid; idx < 4 * 6 * 64; idx += NTHR) {
        int bb = idx & 63; int rest = idx >> 6;
        int f = rest % 6; int jj = rest / 6;
        int jg = cta * 4 + jj;
        float v;
        switch (f) {
            case 0:  v = tanhf(init[0 * H_ + jg]);     break;
            case 1:  v = sigf (init[5 * H_ + jg]);     break;
            case 2:  v = tanhf(init[2 * H_ + jg]);     break;
            case 3:  v = tanhf(init[3 * H_ + jg]);     break;
            case 4:  v = softplusf(init[4 * H_ + jg]); break;
            default: v = tanhf(init[1 * H_ + jg]);     break;
        }
        out[(size_t)bb * (513 * OUTW) + f * H_ + jg] = v;
    }

    // ---- per-(b,j) recurrent state ----
    float c_d = tanhf(init[H_ + ej]);
    float c_b = tanhf(init[2 * H_ + ej]);

    // publish offsets for this thread's h element (k = ej)
    const uint32_t off_hi = aimg_off(eb, ej);
    const uint32_t off_lo = aimg_off(eb + 64, ej);

    int sense = 0;
    // initial grid sync (atomic; total flips 1+511 = 512, even -> replay safe)
    __threadfence();
    __syncthreads();
    if (tid == 0) {
        int s = sense ^ 1; sense = s;
        if (atomicAdd(&g_count, 1) == (int)gridDim.x - 1) {
            g_count = 0; __threadfence(); g_sense = s;
        } else {
            while (g_sense != s) { __nanosleep(64); }
            __threadfence();
        }
    }
    __syncthreads();

    for (int t = 0; t < T_; ++t) {
        const unsigned char* img = g_himg[t & 1];

        // ---- stage A image: 8 x 16KB chunks (chunk = mtile) ----
        if (tid == 0) {
            fence_proxy_async_();
#pragma unroll
            for (int c = 0; c < 8; ++c) {
                mbar_expect_tx(mb + 8 * c, 16384);
                bulk_ldgsts(smA + c * 16384, img + c * 16384, 16384, mb + 8 * c);
            }
        }

        // ---- epilogue prefetch ----
        int   m   = __ldg(&marks[eb * T_ + t]);
        float tsv = __ldg(&ts[eb * T_ + t]);
        float tsp = (t > 0) ? __ldg(&ts[eb * T_ + t - 1]) : 0.0f;
        float tgv[7];
        {
            const float* tgp = g_tg + (size_t)m * G7 + ej;
#pragma unroll
            for (int g = 0; g < 7; ++g) tgv[g] = __ldcg(tgp + g * H_);
        }

        // ---- HMMA compute: warp (kh, mp) ----
        float acc[2][4][4];
#pragma unroll
        for (int i = 0; i < 2; ++i)
#pragma unroll
            for (int j = 0; j < 4; ++j)
#pragma unroll
                for (int q = 0; q < 4; ++q) acc[i][j][q] = 0.0f;

#pragma unroll
        for (int mti = 0; mti < 2; ++mti) {
            const int mt = mp * 2 + mti;
            mbar_wait(mb + 8 * mt, t & 1);
            const uint32_t abase = smA + ((uint32_t)(mt * 32) * 32 + lane) * 16;
            for (int kt = kh * 16; kt < kh * 16 + 16; ++kt) {
                uint32_t a0, a1, a2, a3;
                asm volatile("ld.shared.v4.b32 {%0,%1,%2,%3}, [%4];"
                             : "=r"(a0), "=r"(a1), "=r"(a2), "=r"(a3)
                             : "r"(abase + (uint32_t)kt * (32 * 16)));
#pragma unroll
                for (int pass = 0; pass < 2; ++pass) {
                    const uint32_t* wp = wf + (size_t)(((pass * 32 + kt) * 4) * 32 + lane) * 2;
#pragma unroll
                    for (int nt = 0; nt < 4; ++nt) {
                        uint32_t b0 = wp[nt * 64];
                        uint32_t b1 = wp[nt * 64 + 1];
                        mma16816(acc[mti][nt], a0, a1, a2, a3, b0, b1);
                    }
                }
            }
        }

        // ---- store D fragments to exch[kh] (pad-29 rows) ----
        {
            float* ex = exch + kh * (128 * 29);
#pragma unroll
            for (int mti = 0; mti < 2; ++mti) {
                const int mt = mp * 2 + mti;
#pragma unroll
                for (int nt = 0; nt < 4; ++nt) {
#pragma unroll
                    for (int q = 0; q < 4; ++q) {
                        int row = mt * 16 + grp + ((q >> 1) * 8);
                        int n   = nt * 8 + tg4 * 2 + (q & 1);
                        ex[row * 29 + n] = acc[mti][nt][q];
                    }
                }
            }
        }
        __syncthreads();

        // ---- epilogue: 256 threads, one (b,j) each ----
        float go, cb, c, gd, cd, hd;
        {
            float a[7];
#pragma unroll
            for (int g = 0; g < 7; ++g) {
                int n = g * 4 + ejl;
                a[g] = exch[eb * 29 + n] + exch[(eb + 64) * 29 + n]
                     + exch[128 * 29 + eb * 29 + n] + exch[128 * 29 + (eb + 64) * 29 + n];
            }

            float dur = tsv - tsp;
            float gi  = sigf (a[0] + tgv[0]);
            float gf  = sigf (a[1] + tgv[1]);
            float gz  = tanhf(a[2] + tgv[2]);
            go  = sigf (a[3] + tgv[3]);
            float gib = sigf (a[4] + tgv[4]);
            float gfb = sigf (a[5] + tgv[5]);
            gd  = softplusf(a[6] + tgv[6]);

            c  = gf * c_d + gi * gz;
            cb = gfb * c_b + gib * gz;
            cd = cb + (c - cb) * expf(-gd * dur);
            hd = go * tanhf(cd);
            c_d = cd; c_b = cb;

            // publish h(t+1) into fragment-order image
            __nv_bfloat16 hi = __float2bfloat16(hd);
            __nv_bfloat16 lo = __float2bfloat16(hd - __bfloat162float(hi));
            unsigned char* dst = g_himg[(t + 1) & 1];
            *(__nv_bfloat16*)(dst + off_hi) = hi;
            *(__nv_bfloat16*)(dst + off_lo) = lo;
        }

        // ---- split grid barrier: arrive, hide output STGs under the wait ----
        const bool last = (t == T_ - 1);
        int s_loc = 0;
        __threadfence();
        __syncthreads();
        if (tid == 0 && !last) {
            s_loc = sense ^ 1; sense = s_loc;
            if (atomicAdd(&g_count, 1) == (int)gridDim.x - 1) {
                g_count = 0;
                __threadfence();
                g_sense = s_loc;
            }
        }

        {
            size_t ob = (size_t)eb * (513 * OUTW) + (size_t)(t + 1) * OUTW + ej;
            out[ob]          = hd;
            out[ob + 1 * H_] = go;
            out[ob + 2 * H_] = cb;
            out[ob + 3 * H_] = c;
            out[ob + 4 * H_] = gd;
            out[ob + 5 * H_] = cd;
        }

        if (!last) {
            if (tid == 0) {
                while (g_sense != s_loc) { __nanosleep(64); }
                __threadfence();
            }
            __syncthreads();
        }
    }
}

// =====================  launch  =====================
extern "C" void kernel_launch(void* const* d_in, const int* in_sizes, int n_in,
                              void* d_out, int out_size)
{
    const int*   marks = (const int*)  d_in[0];
    const float* ts    = (const float*)d_in[1];
    const float* emb   = (const float*)d_in[2];
    const float* Wc    = (const float*)d_in[3];
    const float* bc    = (const float*)d_in[4];
    const float* init  = (const float*)d_in[5];
    float*       out   = (float*)d_out;

    dim3 g1(G7 / 256, (C_ + 15) / 16);
    tg_kernel<<<g1, 256>>>(emb, Wc, bc);

    cudaFuncSetAttribute(rec_kernel, cudaFuncAttributeMaxDynamicSharedMemorySize, SMEM_BYTES);
    rec_kernel<<<NCTA, NTHR, SMEM_BYTES>>>(marks, ts, Wc, init, out);
}

// round 14
// speedup vs baseline: 1.4467x; 1.0474x over previous
#include <cuda_runtime.h>
#include <cuda_bf16.h>
#include <cstdint>

#define B_   64
#define T_   512
#define H_   512
#define E_   128
#define C_   1000
#define G7   (7 * H_)    // 3584
#define OUTW (6 * H_)    // 3072
#define NCTA 128
#define NTHR 512

typedef unsigned long long ull;

// ---- device-global scratch ----
__device__ float g_tg[C_ * G7];                      // table_gates (14.3 MB)
__device__ __align__(128) unsigned char g_himg[2][131072];  // A-image, kt-major fragment order
__device__ int           g_count;
__device__ volatile int  g_sense;
__device__ int           g_cnt[4];                   // per-group cumulative publish counters

// ---- math helpers ----
__device__ __forceinline__ float sigf(float x)      { return 1.0f / (1.0f + expf(-x)); }
__device__ __forceinline__ float softplusf(float x) { return fmaxf(x, 0.0f) + log1pf(expf(-fabsf(x))); }

__device__ __forceinline__ uint32_t smem_u32(const void* p)
{
    uint32_t a;
    asm("{ .reg .u64 t; cvta.to.shared.u64 t, %1; cvt.u32.u64 %0, t; }" : "=r"(a) : "l"(p));
    return a;
}
__device__ __forceinline__ int ld_acq(const int* p)
{
    int v;
    asm volatile("ld.acquire.gpu.global.s32 %0, [%1];" : "=r"(v) : "l"(p) : "memory");
    return v;
}
__device__ __forceinline__ void mbar_init(uint32_t mbar, uint32_t cnt)
{
    asm volatile("mbarrier.init.shared.b64 [%0], %1;" :: "r"(mbar), "r"(cnt) : "memory");
}
__device__ __forceinline__ void mbar_expect_tx(uint32_t mbar, uint32_t bytes)
{
    asm volatile("mbarrier.arrive.expect_tx.shared.b64 _, [%0], %1;" :: "r"(mbar), "r"(bytes) : "memory");
}
__device__ __forceinline__ void bulk_ldgsts(uint32_t dst, const void* src, uint32_t bytes, uint32_t mbar)
{
    asm volatile("cp.async.bulk.shared::cta.global.mbarrier::complete_tx::bytes [%0], [%1], %2, [%3];"
                 :: "r"(dst), "l"(src), "r"(bytes), "r"(mbar) : "memory");
}
__device__ __forceinline__ void mbar_wait(uint32_t mbar, uint32_t parity)
{
    uint32_t done;
    asm volatile(
        "{\n\t.reg .pred p;\n\t"
        "mbarrier.try_wait.parity.acquire.cta.shared::cta.b64 p, [%1], %2;\n\t"
        "selp.b32 %0, 1, 0, p;\n\t}"
        : "=r"(done) : "r"(mbar), "r"(parity) : "memory");
    if (!done) {
        asm volatile(
            "{\n\t.reg .pred P1;\n\t"
            "WL_%=:\n\t"
            "mbarrier.try_wait.parity.acquire.cta.shared::cta.b64 P1, [%0], %1, 0x989680;\n\t"
            "@P1 bra.uni WD_%=;\n\t"
            "bra.uni WL_%=;\n\t"
            "WD_%=:\n\t}"
            :: "r"(mbar), "r"(parity) : "memory");
    }
}
__device__ __forceinline__ void fence_proxy_async_()
{
    asm volatile("fence.proxy.async;" ::: "memory");
}

// bf16 mma.sync (baseline PTX, sm_80+)
__device__ __forceinline__ void mma16816(float* d,
                                         uint32_t a0, uint32_t a1, uint32_t a2, uint32_t a3,
                                         uint32_t b0, uint32_t b1)
{
    asm volatile(
        "mma.sync.aligned.m16n8k16.row.col.f32.bf16.bf16.f32 "
        "{%0,%1,%2,%3}, {%4,%5,%6,%7}, {%8,%9}, {%0,%1,%2,%3};"
        : "+f"(d[0]), "+f"(d[1]), "+f"(d[2]), "+f"(d[3])
        : "r"(a0), "r"(a1), "r"(a2), "r"(a3), "r"(b0), "r"(b1));
}

// ---- smem layout (bytes) ----
#define A_OFF      0                  // A image: [ktile32][mtile8][lane32][reg4] x 4B = 131072
#define WF_OFF     131072             // W fragments: [pass2][ktile32][ntile4][lane32] x 8B = 65536
#define EXCH_OFF   196608             // 2 x 128 x 29 fp32 = 29696
#define MBAR_OFF   226304             // 4 chunk mbarriers
#define SMEM_BYTES (MBAR_OFF + 64)    // 226368

// A-image offset for element (m in 0..127, k in 0..511), kt-major chunking
__device__ __forceinline__ uint32_t aimg_off(int m, int k)
{
    int mt = m >> 4, mr = m & 15;
    int kt = k >> 4, kr = k & 15;
    int lane = ((mr & 7) << 2) | ((kr >> 1) & 3);
    int reg  = ((mr >> 3) & 1) | ((kr & 8) ? 2 : 0);
    return ((((uint32_t)(kt * 8 + mt) * 32 + lane) * 4 + reg) * 4) + ((kr & 1) * 2);
}

// atomic grid sync (init only; called twice -> even parity, replay safe)
__device__ __forceinline__ void grid_sync_init()
{
    __threadfence();
    __syncthreads();
    if (threadIdx.x == 0) {
        static __shared__ int s_sense;
        // use a per-call local: emulate with load of g_sense
        int s = g_sense ^ 1;
        (void)s_sense;
        if (atomicAdd(&g_count, 1) == (int)gridDim.x - 1) {
            g_count = 0;
            __threadfence();
            g_sense = s;
        } else {
            while (g_sense != s) { __nanosleep(64); }
            __threadfence();
        }
    }
    __syncthreads();
}

// =====================  Kernel 1: table_gates  =====================
__global__ void tg_kernel(const float* __restrict__ emb,
                          const float* __restrict__ W,
                          const float* __restrict__ bias)
{
    __shared__ float sh_e[16][E_];
    const int col = blockIdx.x * 256 + threadIdx.x;
    const int c0  = blockIdx.y * 16;

    for (int i = threadIdx.x; i < 16 * E_; i += 256) {
        int ci = i >> 7, e = i & 127;
        int c  = c0 + ci;
        sh_e[ci][e] = (c < C_) ? emb[c * E_ + e] : 0.0f;
    }
    __syncthreads();

    float acc[16];
#pragma unroll
    for (int i = 0; i < 16; ++i) acc[i] = 0.0f;

    for (int e = 0; e < E_; ++e) {
        float wv = W[e * G7 + col];
#pragma unroll
        for (int i = 0; i < 16; ++i) acc[i] = fmaf(sh_e[i][e], wv, acc[i]);
    }
    float bb = bias[col];
#pragma unroll
    for (int i = 0; i < 16; ++i) {
        int c = c0 + i;
        if (c < C_) g_tg[c * G7 + col] = acc[i] + bb;
    }
}

// =====================  Kernel 2: persistent HMMA, barrier-free pipeline  =====================
// 128 CTAs x 512 threads. Warp wid: mt = wid & 7 (mtile), kh = wid >> 3 (k-half).
// Chunk c = kt in [8c, 8c+8) = k in [128c,128c+128), produced by CTA group c (32c..32c+31).
// Cross-CTA sync: cumulative per-group counters; CTAs drift at most 1 step.
__global__ void __launch_bounds__(NTHR, 1)
rec_kernel(const int*   __restrict__ marks,
           const float* __restrict__ ts,
           const float* __restrict__ Wc,
           const float* __restrict__ init,
           float*       __restrict__ out)
{
    extern __shared__ unsigned char smem[];
    uint32_t*      wf   = (uint32_t*)(smem + WF_OFF);    // [pass][kt][nt][lane] uint2
    float*         exch = (float*)(smem + EXCH_OFF);     // [kh][128][29]
    const uint32_t mb   = smem_u32(smem + MBAR_OFF);
    const uint32_t smA  = smem_u32(smem + A_OFF);

    const int tid  = threadIdx.x;
    const int cta  = blockIdx.x;
    const int lane = tid & 31;
    const int wid  = tid >> 5;
    const int mt   = wid & 7;        // this warp's mtile
    const int kh   = wid >> 3;       // k-half: kt in [16kh, 16kh+16)
    const int grp  = lane >> 2;
    const int tg4  = lane & 3;

    const int eb   = tid >> 2;       // epilogue batch (tid < 256)
    const int ejl  = tid & 3;
    const int ej   = cta * 4 + ejl;

    if (tid == 0) {
#pragma unroll
        for (int c = 0; c < 4; ++c) mbar_init(mb + 8 * c, 1);
    }
    if (cta == 0 && tid < 4) g_cnt[tid] = 0;

    // ---- prepack W fragments (hi pass 0 / lo pass 1), B-fragment order ----
    for (int idx = tid; idx < 8192; idx += NTHR) {
        int l    = idx & 31;
        int nt   = (idx >> 5) & 3;
        int kt   = (idx >> 7) & 31;
        int pass = idx >> 12;
        int n    = nt * 8 + (l >> 2);
        int k0   = kt * 16 + (l & 3) * 2;
        float w[4];
#pragma unroll
        for (int i = 0; i < 4; ++i) {
            int k = k0 + (i & 1) + ((i >> 1) * 8);
            float v = 0.0f;
            if (n < 28) v = Wc[(size_t)(E_ + k) * G7 + (n >> 2) * H_ + cta * 4 + (n & 3)];
            if (pass == 0) w[i] = __bfloat162float(__float2bfloat16(v));
            else           w[i] = v - __bfloat162float(__float2bfloat16(v));
        }
        __nv_bfloat162 r0, r1;
        r0.x = __float2bfloat16(w[0]); r0.y = __float2bfloat16(w[1]);
        r1.x = __float2bfloat16(w[2]); r1.y = __float2bfloat16(w[3]);
        wf[idx * 2]     = *(uint32_t*)&r0;
        wf[idx * 2 + 1] = *(uint32_t*)&r1;
    }

    // ---- init h image t=0 (this CTA's 4 k columns, all 128 m rows) ----
    for (int idx = tid; idx < 512; idx += NTHR) {
        int m = idx >> 2;
        int k = cta * 4 + (idx & 3);
        float v = tanhf(init[k]);
        __nv_bfloat16 hi = __float2bfloat16(v);
        __nv_bfloat16 val = (m < 64) ? hi : __float2bfloat16(v - __bfloat162float(hi));
        *(__nv_bfloat16*)(g_himg[0] + aimg_off(m, k)) = val;
    }

    // ---- output row t=0 ----
    for (int idx = tid; idx < 4 * 6 * 64; idx += NTHR) {
        int bb = idx & 63; int rest = idx >> 6;
        int f = rest % 6; int jj = rest / 6;
        int jg = cta * 4 + jj;
        float v;
        switch (f) {
            case 0:  v = tanhf(init[0 * H_ + jg]);     break;
            case 1:  v = sigf (init[5 * H_ + jg]);     break;
            case 2:  v = tanhf(init[2 * H_ + jg]);     break;
            case 3:  v = tanhf(init[3 * H_ + jg]);     break;
            case 4:  v = softplusf(init[4 * H_ + jg]); break;
            default: v = tanhf(init[1 * H_ + jg]);     break;
        }
        out[(size_t)bb * (513 * OUTW) + f * H_ + jg] = v;
    }

    // ---- per-(b,j) recurrent state ----
    float c_d = tanhf(init[H_ + ej]);
    float c_b = tanhf(init[2 * H_ + ej]);

    const uint32_t off_hi = aimg_off(eb, ej);
    const uint32_t off_lo = aimg_off(eb + 64, ej);

    // ---- two init grid syncs: h0/counters visible; even parity per launch ----
    grid_sync_init();
    grid_sync_init();

    for (int t = 0; t < T_; ++t) {
        const unsigned char* img = g_himg[t & 1];

        // ---- thread 0: gate on producer groups, then stage chunks ----
        if (tid == 0) {
            const int need = 32 * t;
            fence_proxy_async_();
#pragma unroll
            for (int c = 0; c < 4; ++c) {
                while (ld_acq(&g_cnt[c]) < need) { __nanosleep(32); }
                __threadfence();
                fence_proxy_async_();
                mbar_expect_tx(mb + 8 * c, 32768);
                bulk_ldgsts(smA + c * 32768, img + c * 32768, 32768, mb + 8 * c);
            }
        }

        // ---- epilogue prefetch ----
        int   m   = 0; float tsv = 0.f, tsp = 0.f, tgv[7];
        if (tid < 256) {
            m   = __ldg(&marks[eb * T_ + t]);
            tsv = __ldg(&ts[eb * T_ + t]);
            tsp = (t > 0) ? __ldg(&ts[eb * T_ + t - 1]) : 0.0f;
            const float* tgp = g_tg + (size_t)m * G7 + ej;
#pragma unroll
            for (int g = 0; g < 7; ++g) tgv[g] = __ldcg(tgp + g * H_);
        }

        // ---- HMMA compute: warp (kh, mt) ----
        float acc[4][4];
#pragma unroll
        for (int j = 0; j < 4; ++j)
#pragma unroll
            for (int q = 0; q < 4; ++q) acc[j][q] = 0.0f;

        const uint32_t abase = smA + ((uint32_t)mt * 32 + lane) * 16;
#pragma unroll
        for (int half = 0; half < 2; ++half) {
            const int c = kh * 2 + half;
            mbar_wait(mb + 8 * c, t & 1);
            const int kt0 = c * 8;
#pragma unroll
            for (int kti = 0; kti < 8; ++kti) {
                const int kt = kt0 + kti;
                uint32_t a0, a1, a2, a3;
                asm volatile("ld.shared.v4.b32 {%0,%1,%2,%3}, [%4];"
                             : "=r"(a0), "=r"(a1), "=r"(a2), "=r"(a3)
                             : "r"(abase + (uint32_t)kt * 4096));
#pragma unroll
                for (int pass = 0; pass < 2; ++pass) {
                    const uint32_t* wp = wf + (size_t)(((pass * 32 + kt) * 4) * 32 + lane) * 2;
#pragma unroll
                    for (int nt = 0; nt < 4; ++nt) {
                        mma16816(acc[nt], a0, a1, a2, a3, wp[nt * 64], wp[nt * 64 + 1]);
                    }
                }
            }
        }

        // ---- store D fragments to exch[kh] ----
        {
            float* ex = exch + kh * (128 * 29);
#pragma unroll
            for (int nt = 0; nt < 4; ++nt) {
#pragma unroll
                for (int q = 0; q < 4; ++q) {
                    int row = mt * 16 + grp + ((q >> 1) * 8);
                    int n   = nt * 8 + tg4 * 2 + (q & 1);
                    ex[row * 29 + n] = acc[nt][q];
                }
            }
        }
        __syncthreads();

        // ---- epilogue: 256 threads, one (b,j) each ----
        float go = 0.f, cb = 0.f, c = 0.f, gd = 0.f, cd = 0.f, hd = 0.f;
        if (tid < 256) {
            float a[7];
#pragma unroll
            for (int g = 0; g < 7; ++g) {
                int n = g * 4 + ejl;
                a[g] = exch[eb * 29 + n] + exch[(eb + 64) * 29 + n]
                     + exch[128 * 29 + eb * 29 + n] + exch[128 * 29 + (eb + 64) * 29 + n];
            }

            float dur = tsv - tsp;
            float gi  = sigf (a[0] + tgv[0]);
            float gf  = sigf (a[1] + tgv[1]);
            float gz  = tanhf(a[2] + tgv[2]);
            go  = sigf (a[3] + tgv[3]);
            float gib = sigf (a[4] + tgv[4]);
            float gfb = sigf (a[5] + tgv[5]);
            gd  = softplusf(a[6] + tgv[6]);

            c  = gf * c_d + gi * gz;
            cb = gfb * c_b + gib * gz;
            cd = cb + (c - cb) * expf(-gd * dur);
            hd = go * tanhf(cd);
            c_d = cd; c_b = cb;

            // publish h(t+1) into fragment-order image
            __nv_bfloat16 hi = __float2bfloat16(hd);
            __nv_bfloat16 lo = __float2bfloat16(hd - __bfloat162float(hi));
            unsigned char* dst = g_himg[(t + 1) & 1];
            *(__nv_bfloat16*)(dst + off_hi) = hi;
            *(__nv_bfloat16*)(dst + off_lo) = lo;
        }

        // ---- release: publishes visible, then bump group counter ----
        __threadfence();
        __syncthreads();
        if (tid == 0) atomicAdd(&g_cnt[cta >> 5], 1);

        // ---- off critical path: fp32 outputs ----
        if (tid < 256) {
            size_t ob = (size_t)eb * (513 * OUTW) + (size_t)(t + 1) * OUTW + ej;
            out[ob]          = hd;
            out[ob + 1 * H_] = go;
            out[ob + 2 * H_] = cb;
            out[ob + 3 * H_] = c;
            out[ob + 4 * H_] = gd;
            out[ob + 5 * H_] = cd;
        }
    }
}

// =====================  launch  =====================
extern "C" void kernel_launch(void* const* d_in, const int* in_sizes, int n_in,
                              void* d_out, int out_size)
{
    const int*   marks = (const int*)  d_in[0];
    const float* ts    = (const float*)d_in[1];
    const float* emb   = (const float*)d_in[2];
    const float* Wc    = (const float*)d_in[3];
    const float* bc    = (const float*)d_in[4];
    const float* init  = (const float*)d_in[5];
    float*       out   = (float*)d_out;

    dim3 g1(G7 / 256, (C_ + 15) / 16);
    tg_kernel<<<g1, 256>>>(emb, Wc, bc);

    cudaFuncSetAttribute(rec_kernel, cudaFuncAttributeMaxDynamicSharedMemorySize, SMEM_BYTES);
    rec_kernel<<<NCTA, NTHR, SMEM_BYTES>>>(marks, ts, Wc, init, out);
}

// round 15
// speedup vs baseline: 1.5851x; 1.0956x over previous
#include <cuda_runtime.h>
#include <cuda_bf16.h>
#include <cstdint>

#define B_   64
#define T_   512
#define H_   512
#define E_   128
#define C_   1000
#define G7   (7 * H_)    // 3584
#define OUTW (6 * H_)    // 3072
#define NCTA 128
#define NTHR 544         // 16 consumer warps + 1 producer warp

typedef unsigned long long ull;

// ---- device-global scratch ----
__device__ float g_tg[C_ * G7];                          // table_gates (14.3 MB)
__device__ __align__(128) unsigned char g_himg[2][2][65536];  // [half][parity] A-image (fragment order)
__device__ int           g_count;
__device__ volatile int  g_sense;
__device__ int           g_cnt[8];                       // [half*4 + group] cumulative publish counters

// ---- math helpers ----
__device__ __forceinline__ float sigf(float x)      { return 1.0f / (1.0f + expf(-x)); }
__device__ __forceinline__ float softplusf(float x) { return fmaxf(x, 0.0f) + log1pf(expf(-fabsf(x))); }

__device__ __forceinline__ uint32_t smem_u32(const void* p)
{
    uint32_t a;
    asm("{ .reg .u64 t; cvta.to.shared.u64 t, %1; cvt.u32.u64 %0, t; }" : "=r"(a) : "l"(p));
    return a;
}
__device__ __forceinline__ int ld_acq(const int* p)
{
    int v;
    asm volatile("ld.acquire.gpu.global.s32 %0, [%1];" : "=r"(v) : "l"(p) : "memory");
    return v;
}
__device__ __forceinline__ void mbar_init(uint32_t mbar, uint32_t cnt)
{
    asm volatile("mbarrier.init.shared.b64 [%0], %1;" :: "r"(mbar), "r"(cnt) : "memory");
}
__device__ __forceinline__ void mbar_expect_tx(uint32_t mbar, uint32_t bytes)
{
    asm volatile("mbarrier.arrive.expect_tx.shared.b64 _, [%0], %1;" :: "r"(mbar), "r"(bytes) : "memory");
}
__device__ __forceinline__ void mbar_arrive(uint32_t mbar)
{
    asm volatile("mbarrier.arrive.shared.b64 _, [%0];" :: "r"(mbar) : "memory");
}
__device__ __forceinline__ void bulk_ldgsts(uint32_t dst, const void* src, uint32_t bytes, uint32_t mbar)
{
    asm volatile("cp.async.bulk.shared::cta.global.mbarrier::complete_tx::bytes [%0], [%1], %2, [%3];"
                 :: "r"(dst), "l"(src), "r"(bytes), "r"(mbar) : "memory");
}
__device__ __forceinline__ void mbar_wait(uint32_t mbar, uint32_t parity)
{
    uint32_t done;
    asm volatile(
        "{\n\t.reg .pred p;\n\t"
        "mbarrier.try_wait.parity.acquire.cta.shared::cta.b64 p, [%1], %2;\n\t"
        "selp.b32 %0, 1, 0, p;\n\t}"
        : "=r"(done) : "r"(mbar), "r"(parity) : "memory");
    if (!done) {
        asm volatile(
            "{\n\t.reg .pred P1;\n\t"
            "WL_%=:\n\t"
            "mbarrier.try_wait.parity.acquire.cta.shared::cta.b64 P1, [%0], %1, 0x989680;\n\t"
            "@P1 bra.uni WD_%=;\n\t"
            "bra.uni WL_%=;\n\t"
            "WD_%=:\n\t}"
            :: "r"(mbar), "r"(parity) : "memory");
    }
}
__device__ __forceinline__ void fence_proxy_async_()
{
    asm volatile("fence.proxy.async;" ::: "memory");
}
#define BAR1() asm volatile("bar.sync 1, 512;" ::: "memory")

// bf16 mma.sync (baseline PTX, sm_80+)
__device__ __forceinline__ void mma16816(float* d,
                                         uint32_t a0, uint32_t a1, uint32_t a2, uint32_t a3,
                                         uint32_t b0, uint32_t b1)
{
    asm volatile(
        "mma.sync.aligned.m16n8k16.row.col.f32.bf16.bf16.f32 "
        "{%0,%1,%2,%3}, {%4,%5,%6,%7}, {%8,%9}, {%0,%1,%2,%3};"
        : "+f"(d[0]), "+f"(d[1]), "+f"(d[2]), "+f"(d[3])
        : "r"(a0), "r"(a1), "r"(a2), "r"(a3), "r"(b0), "r"(b1));
}

// ---- smem layout (bytes) ----
#define A0_OFF     0                  // half0 A buffer: 64KB
#define A1_OFF     65536              // half1 A buffer: 64KB
#define WF_OFF     131072             // W fragments: 64KB
#define EXCH_OFF   196608             // 4 x 64 x 29 fp32 = 29696
#define MBAR_OFF   226304             // full[2][4] (64B) + consumed[2] (16B)
#define SMEM_BYTES (MBAR_OFF + 128)   // 226432

// half A-image offset for element (m in 0..63, k in 0..511); chunk c = kt in [8c,8c+8) = 16KB
__device__ __forceinline__ uint32_t aimg_off(int m, int k)
{
    int mt = m >> 4, mr = m & 15;
    int kt = k >> 4, kr = k & 15;
    int lane = ((mr & 7) << 2) | ((kr >> 1) & 3);
    int reg  = ((mr >> 3) & 1) | ((kr & 8) ? 2 : 0);
    return ((((uint32_t)(kt * 4 + mt) * 32 + lane) * 4 + reg) * 4) + ((kr & 1) * 2);
}

// atomic grid sync (init only; called twice -> even parity per launch, replay safe)
__device__ __forceinline__ void grid_sync_init(int* sense)
{
    __threadfence();
    __syncthreads();
    if (threadIdx.x == 0) {
        int s = *sense ^ 1;
        *sense = s;
        if (atomicAdd(&g_count, 1) == (int)gridDim.x - 1) {
            g_count = 0;
            __threadfence();
            g_sense = s;
        } else {
            while (g_sense != s) { __nanosleep(64); }
            __threadfence();
        }
    }
    __syncthreads();
}

// =====================  Kernel 1: table_gates  =====================
__global__ void tg_kernel(const float* __restrict__ emb,
                          const float* __restrict__ W,
                          const float* __restrict__ bias)
{
    __shared__ float sh_e[16][E_];
    const int col = blockIdx.x * 256 + threadIdx.x;
    const int c0  = blockIdx.y * 16;

    for (int i = threadIdx.x; i < 16 * E_; i += 256) {
        int ci = i >> 7, e = i & 127;
        int c  = c0 + ci;
        sh_e[ci][e] = (c < C_) ? emb[c * E_ + e] : 0.0f;
    }
    __syncthreads();

    float acc[16];
#pragma unroll
    for (int i = 0; i < 16; ++i) acc[i] = 0.0f;

    for (int e = 0; e < E_; ++e) {
        float wv = W[e * G7 + col];
#pragma unroll
        for (int i = 0; i < 16; ++i) acc[i] = fmaf(sh_e[i][e], wv, acc[i]);
    }
    float bb = bias[col];
#pragma unroll
    for (int i = 0; i < 16; ++i) {
        int c = c0 + i;
        if (c < C_) g_tg[c * G7 + col] = acc[i] + bb;
    }
}

// =====================  Kernel 2: persistent HMMA, two interleaved half-batch chains  =====================
// 128 CTAs x 544 threads. Consumer warps 0..15: mt = wid & 3, kq = wid >> 2 (kq == chunk id).
// Producer warp 16 (tid 512): polls counters, issues TMA 2 sub-steps ahead.
// Chunk c = k in [128c,128c+128), produced by CTA group c (32c..32c+31).
__global__ void __launch_bounds__(NTHR, 1)
rec_kernel(const int*   __restrict__ marks,
           const float* __restrict__ ts,
           const float* __restrict__ Wc,
           const float* __restrict__ init,
           float*       __restrict__ out)
{
    extern __shared__ unsigned char smem[];
    uint32_t*      wf   = (uint32_t*)(smem + WF_OFF);
    float*         exch = (float*)(smem + EXCH_OFF);     // [kq4][64][29]
    const uint32_t mb   = smem_u32(smem + MBAR_OFF);     // full[buf][c] = mb + (buf*4+c)*8 ; consumed[buf] = mb+64+8*buf
    const uint32_t smA0 = smem_u32(smem + A0_OFF);

    const int tid  = threadIdx.x;
    const int cta  = blockIdx.x;
    const int lane = tid & 31;
    const int wid  = tid >> 5;
    const int mt   = wid & 3;        // consumer: mtile 0..3
    const int kq   = wid >> 2;       // consumer: chunk 0..3 (wid<16)
    const int grp  = lane >> 2;
    const int tg4  = lane & 3;

    const int eb32 = tid >> 2;       // epilogue local batch (tid < 128)
    const int ejl  = tid & 3;
    const int ej   = cta * 4 + ejl;

    if (tid == 0) {
#pragma unroll
        for (int i = 0; i < 8; ++i) mbar_init(mb + i * 8, 1);       // full barriers
        mbar_init(mb + 64, 16);                                     // consumed[0]
        mbar_init(mb + 72, 16);                                     // consumed[1]
    }
    if (cta == 0 && tid < 8) g_cnt[tid] = 0;

    // ---- prepack W fragments (hi pass 0 / lo pass 1), B-fragment order ----
    for (int idx = tid; idx < 8192; idx += NTHR) {
        int l    = idx & 31;
        int nt   = (idx >> 5) & 3;
        int kt   = (idx >> 7) & 31;
        int pass = idx >> 12;
        int n    = nt * 8 + (l >> 2);
        int k0   = kt * 16 + (l & 3) * 2;
        float w[4];
#pragma unroll
        for (int i = 0; i < 4; ++i) {
            int k = k0 + (i & 1) + ((i >> 1) * 8);
            float v = 0.0f;
            if (n < 28) v = Wc[(size_t)(E_ + k) * G7 + (n >> 2) * H_ + cta * 4 + (n & 3)];
            if (pass == 0) w[i] = __bfloat162float(__float2bfloat16(v));
            else           w[i] = v - __bfloat162float(__float2bfloat16(v));
        }
        __nv_bfloat162 r0, r1;
        r0.x = __float2bfloat16(w[0]); r0.y = __float2bfloat16(w[1]);
        r1.x = __float2bfloat16(w[2]); r1.y = __float2bfloat16(w[3]);
        wf[idx * 2]     = *(uint32_t*)&r0;
        wf[idx * 2 + 1] = *(uint32_t*)&r1;
    }

    // ---- init h images t=0 (this CTA's 4 k columns; both halves, hi+lo rows) ----
    for (int idx = tid; idx < 512; idx += NTHR) {
        int b    = idx >> 3;
        int jj   = (idx >> 1) & 3;
        int hilo = idx & 1;
        int k    = cta * 4 + jj;
        float v  = tanhf(init[k]);
        __nv_bfloat16 hi = __float2bfloat16(v);
        __nv_bfloat16 val = hilo ? __float2bfloat16(v - __bfloat162float(hi)) : hi;
        int half = b >> 5;
        int m    = (b & 31) + hilo * 32;
        *(__nv_bfloat16*)(g_himg[half][0] + aimg_off(m, k)) = val;
    }

    // ---- output row t=0 ----
    for (int idx = tid; idx < 4 * 6 * 64; idx += NTHR) {
        int bb = idx & 63; int rest = idx >> 6;
        int f = rest % 6; int jj = rest / 6;
        int jg = cta * 4 + jj;
        float v;
        switch (f) {
            case 0:  v = tanhf(init[0 * H_ + jg]);     break;
            case 1:  v = sigf (init[5 * H_ + jg]);     break;
            case 2:  v = tanhf(init[2 * H_ + jg]);     break;
            case 3:  v = tanhf(init[3 * H_ + jg]);     break;
            case 4:  v = softplusf(init[4 * H_ + jg]); break;
            default: v = tanhf(init[1 * H_ + jg]);     break;
        }
        out[(size_t)bb * (513 * OUTW) + f * H_ + jg] = v;
    }

    // ---- per-(b,j) recurrent state: same init value for both halves ----
    float cdv[2], cbv[2];
    cdv[0] = cdv[1] = tanhf(init[H_ + ej]);
    cbv[0] = cbv[1] = tanhf(init[2 * H_ + ej]);

    const uint32_t off_hi = aimg_off(eb32, ej);
    const uint32_t off_lo = aimg_off(eb32 + 32, ej);

    // ---- two init grid syncs (h0/counters visible; even parity) ----
    int sense = 0;
    grid_sync_init(&sense);
    grid_sync_init(&sense);

    if (tid >= 513) return;

    // =====================  producer warp thread  =====================
    if (tid == 512) {
        int phc[2] = {0, 0};
        // prologue: issue sub-steps s=0 (half0,t0) and s=1 (half1,t0); gates trivially pass
        fence_proxy_async_();
#pragma unroll
        for (int c = 0; c < 4; ++c) {
            mbar_expect_tx(mb + c * 8, 16384);
            bulk_ldgsts(smA0 + c * 16384, g_himg[0][0] + c * 16384, 16384, mb + c * 8);
        }
#pragma unroll
        for (int c = 0; c < 4; ++c) {
            mbar_expect_tx(mb + (4 + c) * 8, 16384);
            bulk_ldgsts(smA0 + 65536 + c * 16384, g_himg[1][0] + c * 16384, 16384, mb + (4 + c) * 8);
        }
        for (int sp = 2; sp < 1024; ++sp) {
            const int buf = sp & 1;          // buf == half
            const int t   = sp >> 1;
            mbar_wait(mb + 64 + buf * 8, phc[buf]); phc[buf] ^= 1;   // consumers done with this buffer
            const int need = 32 * t;
#pragma unroll
            for (int c = 0; c < 4; ++c) {
                while (ld_acq(&g_cnt[buf * 4 + c]) < need) { __nanosleep(32); }
            }
            fence_proxy_async_();
            const unsigned char* src = g_himg[buf][t & 1];
            const uint32_t dstb = smA0 + buf * 65536;
#pragma unroll
            for (int c = 0; c < 4; ++c) {
                mbar_expect_tx(mb + (buf * 4 + c) * 8, 16384);
                bulk_ldgsts(dstb + c * 16384, src + c * 16384, 16384, mb + (buf * 4 + c) * 8);
            }
        }
        return;
    }

    // =====================  consumer warps (tid < 512)  =====================
    int fph[2] = {0, 0};

    for (int t = 0; t < T_; ++t) {
#pragma unroll
        for (int half = 0; half < 2; ++half) {
            const int buf = half;
            const uint32_t abuf = smA0 + buf * 65536;

            // ---- epilogue prefetch ----
            float tsv = 0.f, tsp = 0.f, tgv[7];
            if (tid < 128) {
                int b = half * 32 + eb32;
                int mk = __ldg(&marks[b * T_ + t]);
                tsv = __ldg(&ts[b * T_ + t]);
                tsp = (t > 0) ? __ldg(&ts[b * T_ + t - 1]) : 0.0f;
                const float* tgp = g_tg + (size_t)mk * G7 + ej;
#pragma unroll
                for (int g = 0; g < 7; ++g) tgv[g] = __ldcg(tgp + g * H_);
            }

            // ---- MMA: warp (kq, mt) waits only its own chunk ----
            float acc[4][4];
#pragma unroll
            for (int j = 0; j < 4; ++j)
#pragma unroll
                for (int q = 0; q < 4; ++q) acc[j][q] = 0.0f;

            mbar_wait(mb + (buf * 4 + kq) * 8, fph[buf]);
            if (half == 1) { fph[1] ^= 1; } else { fph[0] ^= 1; }

            const uint32_t abase = abuf + ((uint32_t)mt * 32 + lane) * 16;
#pragma unroll
            for (int kti = 0; kti < 8; ++kti) {
                const int kt = kq * 8 + kti;
                uint32_t a0, a1, a2, a3;
                asm volatile("ld.shared.v4.b32 {%0,%1,%2,%3}, [%4];"
                             : "=r"(a0), "=r"(a1), "=r"(a2), "=r"(a3)
                             : "r"(abase + (uint32_t)kt * 2048));
#pragma unroll
                for (int pass = 0; pass < 2; ++pass) {
                    const uint32_t* wp = wf + (size_t)(((pass * 32 + kt) * 4) * 32 + lane) * 2;
#pragma unroll
                    for (int nt = 0; nt < 4; ++nt) {
                        mma16816(acc[nt], a0, a1, a2, a3, wp[nt * 64], wp[nt * 64 + 1]);
                    }
                }
            }
            __syncwarp();
            if (lane == 0) mbar_arrive(mb + 64 + buf * 8);   // buffer consumed

            // ---- store D fragments ----
            {
                float* ex = exch + kq * (64 * 29);
#pragma unroll
                for (int nt = 0; nt < 4; ++nt) {
#pragma unroll
                    for (int q = 0; q < 4; ++q) {
                        int row = mt * 16 + grp + ((q >> 1) * 8);
                        int n   = nt * 8 + tg4 * 2 + (q & 1);
                        ex[row * 29 + n] = acc[nt][q];
                    }
                }
            }
            BAR1();

            // ---- epilogue: 128 threads, one (b,j) each ----
            float go = 0.f, cbx = 0.f, cx = 0.f, gd = 0.f, cd = 0.f, hd = 0.f;
            if (tid < 128) {
                float a[7];
#pragma unroll
                for (int g = 0; g < 7; ++g) {
                    int n = g * 4 + ejl;
                    float s = 0.f;
#pragma unroll
                    for (int q2 = 0; q2 < 4; ++q2)
                        s += exch[q2 * (64 * 29) + eb32 * 29 + n]
                           + exch[q2 * (64 * 29) + (eb32 + 32) * 29 + n];
                    a[g] = s;
                }

                float dur = tsv - tsp;
                float gi  = sigf (a[0] + tgv[0]);
                float gf  = sigf (a[1] + tgv[1]);
                float gz  = tanhf(a[2] + tgv[2]);
                go  = sigf (a[3] + tgv[3]);
                float gib = sigf (a[4] + tgv[4]);
                float gfb = sigf (a[5] + tgv[5]);
                gd  = softplusf(a[6] + tgv[6]);

                cx  = gf * cdv[half] + gi * gz;
                cbx = gfb * cbv[half] + gib * gz;
                cd  = cbx + (cx - cbx) * expf(-gd * dur);
                hd  = go * tanhf(cd);
                cdv[half] = cd; cbv[half] = cbx;

                __nv_bfloat16 hi = __float2bfloat16(hd);
                __nv_bfloat16 lo = __float2bfloat16(hd - __bfloat162float(hi));
                unsigned char* dst = g_himg[half][(t + 1) & 1];
                *(__nv_bfloat16*)(dst + off_hi) = hi;
                *(__nv_bfloat16*)(dst + off_lo) = lo;
            }
            __threadfence();
            BAR1();
            if (tid == 0) atomicAdd(&g_cnt[half * 4 + (cta >> 5)], 1);

            // ---- off critical path: fp32 outputs ----
            if (tid < 128) {
                int b = half * 32 + eb32;
                size_t ob = (size_t)b * (513 * OUTW) + (size_t)(t + 1) * OUTW + ej;
                out[ob]          = hd;
                out[ob + 1 * H_] = go;
                out[ob + 2 * H_] = cbx;
                out[ob + 3 * H_] = cx;
                out[ob + 4 * H_] = gd;
                out[ob + 5 * H_] = cd;
            }
        }
    }
}

// =====================  launch  =====================
extern "C" void kernel_launch(void* const* d_in, const int* in_sizes, int n_in,
                              void* d_out, int out_size)
{
    const int*   marks = (const int*)  d_in[0];
    const float* ts    = (const float*)d_in[1];
    const float* emb   = (const float*)d_in[2];
    const float* Wc    = (const float*)d_in[3];
    const float* bc    = (const float*)d_in[4];
    const float* init  = (const float*)d_in[5];
    float*       out   = (float*)d_out;

    dim3 g1(G7 / 256, (C_ + 15) / 16);
    tg_kernel<<<g1, 256>>>(emb, Wc, bc);

    cudaFuncSetAttribute(rec_kernel, cudaFuncAttributeMaxDynamicSharedMemorySize, SMEM_BYTES);
    rec_kernel<<<NCTA, NTHR, SMEM_BYTES>>>(marks, ts, Wc, init, out);
}